// round 9
// baseline (speedup 1.0000x reference)
#include <cuda_runtime.h>
#include <cstdint>
#include <cstddef>

// ---------------- problem constants ----------------
constexpr int E    = 4;
constexpr int Bn   = 32;
constexpr int CIN  = 64;
constexpr int H    = 64;
constexpr int W    = 64;
constexpr int COUT = 128;
constexpr int HO   = 62;
constexpr int WO   = 62;
constexpr int NTAPS = 9;

// ---------------- SMEM layout (byte offsets) ----------------
// G: features tf32 [264 pos][68-word pitch], ch words 0..63 used
constexpr int G_PITCH_W = 68;                    // words per pos row (pad for banks)
constexpr int SM_G     = 0;                      // 264*272 = 71808 B
// W: weight fragments for one tap: 8 mtiles x 8 ks x 32 lanes x 16B = 32768 B
constexpr int SM_W     = 71808;
// stage: fp32 chunk 32 ch x 257 words = 32896 B (UNION with W; prologue only)
constexpr int SM_STAGE = 71808;
constexpr int SM_BIAS  = 71808 + 32896;          // 104704
constexpr int SM_TOTAL = 104704 + 512;           // 105216; x2 blocks = 210432 <= 228KB

constexpr int WBLK = 32768;                      // bytes per (e,tap) fragment block

// ---------------- prepped weights: fragment-packed tf32 ----------------
// [e][tap][mtile(8)][ks(8)][lane(32)] -> uint4 {a0,a1,a2,a3}
__device__ __align__(16) uint4 g_wfrag[E * NTAPS * 8 * 8 * 32];

__device__ __forceinline__ uint32_t f2tf32(float f) {
    uint32_t r;
    asm("cvt.rna.tf32.f32 %0, %1;" : "=r"(r) : "f"(f));
    return r;
}

__global__ void prep_weights_kernel(const float* __restrict__ wgt) {
    int idx = blockIdx.x * blockDim.x + threadIdx.x;
    if (idx >= E * NTAPS * 8 * 8 * 32) return;
    const int lane  = idx & 31;
    const int ks    = (idx >> 5) & 7;
    const int mtile = (idx >> 8) & 7;
    const int et    = idx >> 11;          // 0..35
    const int tap   = et % NTAPS;
    const int e     = et / NTAPS;

    const int g  = lane >> 2;
    const int t4 = lane & 3;
    const int j0 = mtile * 16 + g;
    const int i0 = ks * 8 + t4;

    auto wv = [&](int j, int i) -> float {
        return wgt[(((size_t)e * CIN + i) * COUT + j) * 9 + tap];
    };
    uint4 v;
    v.x = f2tf32(wv(j0,     i0));
    v.y = f2tf32(wv(j0 + 8, i0));
    v.z = f2tf32(wv(j0,     i0 + 4));
    v.w = f2tf32(wv(j0 + 8, i0 + 4));
    g_wfrag[idx] = v;
}

// ---------------- PTX helpers ----------------
__device__ __forceinline__ uint32_t smem_u32(const void* p) {
    uint32_t a;
    asm("{ .reg .u64 t; cvta.to.shared.u64 t, %1; cvt.u32.u64 %0, t; }" : "=r"(a) : "l"(p));
    return a;
}
__device__ __forceinline__ void cpasync16(uint32_t dst, const void* src) {
    asm volatile("cp.async.cg.shared.global [%0], [%1], 16;" :: "r"(dst), "l"(src));
}
__device__ __forceinline__ void cpasync_commit() {
    asm volatile("cp.async.commit_group;" ::: "memory");
}
__device__ __forceinline__ void cpasync_wait0() {
    asm volatile("cp.async.wait_group 0;" ::: "memory");
}
__device__ __forceinline__ void mma_tf32(float* c, const uint32_t* a, uint32_t b0, uint32_t b1) {
    asm volatile(
        "mma.sync.aligned.m16n8k8.row.col.f32.tf32.tf32.f32 "
        "{%0,%1,%2,%3}, {%4,%5,%6,%7}, {%8,%9}, {%0,%1,%2,%3};"
        : "+f"(c[0]), "+f"(c[1]), "+f"(c[2]), "+f"(c[3])
        : "r"(a[0]), "r"(a[1]), "r"(a[2]), "r"(a[3]), "r"(b0), "r"(b1));
}

// ---------------- main kernel ----------------
// 256 threads (8 warps). jbase=(wid&1)*64 (couts, MMA-A), pbase=(wid>>1)*32 (pos, MMA-B).
// Per warp: 4 m16 x 4 n8 tiles; K = 9 taps x 8 k8 steps; single tf32 pass.
__global__ __launch_bounds__(256, 2)
void conv_tf32_kernel(const float* __restrict__ feat,
                      const float* __restrict__ bias,
                      float* __restrict__ out)
{
    extern __shared__ __align__(128) char smem[];
    const int tid  = threadIdx.x;
    const int wid  = tid >> 5;
    const int lane = tid & 31;
    const int g    = lane >> 2;
    const int t4   = lane & 3;
    const int eb   = blockIdx.y;
    const int e    = eb >> 5;
    const int y0   = blockIdx.x * 2;
    const uint32_t sb = smem_u32(smem);

    // --- 0) zero G pad rows (pos 256..263, ch words 0..63), load bias ---
    {
        uint32_t* gz = (uint32_t*)(smem + SM_G);
#pragma unroll
        for (int z = 0; z < 2; z++) {
            int w_ = z * 256 + tid;           // 0..511
            int pr = w_ >> 6, cw = w_ & 63;
            gz[(256 + pr) * G_PITCH_W + cw] = 0u;
        }
        if (tid < 128) ((float*)(smem + SM_BIAS))[tid] = bias[e * COUT + tid];
    }

    // --- 1) stage fp32 + build G (tf32) in two 32-channel chunks ---
    const float* fb = feat + (size_t)eb * CIN * H * W + (size_t)y0 * W;
    float* sf = (float*)(smem + SM_STAGE);
#pragma unroll
    for (int q = 0; q < 2; q++) {
        __syncthreads();
#pragma unroll
        for (int c = 0; c < 32; c++) {
            int idx = c * 256 + tid;
            int i = idx >> 8, rx = idx & 255;
            sf[i * 257 + rx] = fb[(size_t)(q * 32 + i) * (H * W) + rx];
        }
        __syncthreads();
        uint32_t* gw = (uint32_t*)(smem + SM_G);
        const int ch = q * 32 + lane;
#pragma unroll
        for (int it = 0; it < 32; it++) {
            const int p = wid * 32 + it;
            gw[p * G_PITCH_W + ch] = f2tf32(sf[lane * 257 + p]);
        }
    }
    __syncthreads();   // stage dead: W region free

    // --- 2) copy tap-0 weight fragments ---
    {
        const uint4* src = g_wfrag + (size_t)(e * NTAPS) * 2048;
#pragma unroll
        for (int c = 0; c < 8; c++) {
            int off = (c * 256 + tid) * 16;
            cpasync16(sb + SM_W + off, (const char*)src + off);
        }
        cpasync_commit();
        cpasync_wait0();
    }
    __syncthreads();

    // --- 3) main loop: 9 taps x 8 k8 steps ---
    const int jt4   = (wid & 1) * 4;       // first m16 tile index for this warp
    const int pbase = (wid >> 1) * 32;

    float acc[4][4][4];
#pragma unroll
    for (int a = 0; a < 4; a++)
#pragma unroll
        for (int b = 0; b < 4; b++)
#pragma unroll
            for (int c = 0; c < 4; c++) acc[a][b][c] = 0.0f;

    for (int t = 0; t < NTAPS; t++) {
        const int ky = t / 3, kx = t - ky * 3;
        const int pshift = pbase + ky * 64 + kx;
        const uint32_t brow0 = sb + SM_G + (uint32_t)(pshift + g) * (G_PITCH_W * 4);

#pragma unroll
        for (int ks = 0; ks < 8; ks++) {
            uint4 afr[4];
#pragma unroll
            for (int mt = 0; mt < 4; mt++) {
                afr[mt] = *(const uint4*)(smem + SM_W
                          + (((jt4 + mt) * 8 + ks) * 32 + lane) * 16);
            }
            uint32_t bfr[4][2];
            const uint32_t bk = brow0 + (uint32_t)(ks * 8 + t4) * 4;
#pragma unroll
            for (int nt = 0; nt < 4; nt++) {
                const uint32_t ba = bk + (uint32_t)nt * (8 * G_PITCH_W * 4);
                bfr[nt][0] = *(const uint32_t*)(smem + (ba - sb));
                bfr[nt][1] = *(const uint32_t*)(smem + (ba - sb) + 16);
            }
#pragma unroll
            for (int mt = 0; mt < 4; mt++) {
                const uint32_t a_[4] = {afr[mt].x, afr[mt].y, afr[mt].z, afr[mt].w};
#pragma unroll
                for (int nt = 0; nt < 4; nt++) {
                    mma_tf32(acc[mt][nt], a_, bfr[nt][0], bfr[nt][1]);
                }
            }
        }

        // single-buffer weight swap for tap t+1
        if (t < NTAPS - 1) {
            __syncthreads();
            const uint4* src = g_wfrag + (size_t)(e * NTAPS + t + 1) * 2048;
#pragma unroll
            for (int c = 0; c < 8; c++) {
                int off = (c * 256 + tid) * 16;
                cpasync16(sb + SM_W + off, (const char*)src + off);
            }
            cpasync_commit();
            cpasync_wait0();
            __syncthreads();
        }
    }

    // --- 4) epilogue: bias + float2 stores (same accumulator layout as m16n8k16) ---
    const float* sbias = (const float*)(smem + SM_BIAS);
    const int jbase = (wid & 1) * 64;
#pragma unroll
    for (int mt = 0; mt < 4; mt++) {
        const int j0 = jbase + mt * 16 + g;
        const float b0 = sbias[j0];
        const float b1 = sbias[j0 + 8];
#pragma unroll
        for (int q = 0; q < 4; q++) {
            const int pos = pbase + q * 8 + 2 * t4;
            const int x = pos & 63;
            const int y = y0 + (pos >> 6);
            if (x < WO) {
                float2 v0 = make_float2(acc[mt][q][0] + b0, acc[mt][q][1] + b0);
                float2 v1 = make_float2(acc[mt][q][2] + b1, acc[mt][q][3] + b1);
                *(float2*)(out + (((size_t)eb * COUT + j0)     * HO + y) * WO + x) = v0;
                *(float2*)(out + (((size_t)eb * COUT + j0 + 8) * HO + y) * WO + x) = v1;
            }
        }
    }
}

// ---------------- launch ----------------
extern "C" void kernel_launch(void* const* d_in, const int* in_sizes, int n_in,
                              void* d_out, int out_size)
{
    const float* feat = (const float*)d_in[0];  // (E, B, C_in, H, W)
    const float* wgt  = (const float*)d_in[1];  // (E, C_in, C_out, 3, 3)
    const float* bias = (const float*)d_in[2];  // (E, C_out)
    float*       out  = (float*)d_out;          // (E, B, C_out, 62, 62)

    cudaFuncSetAttribute(conv_tf32_kernel,
                         cudaFuncAttributeMaxDynamicSharedMemorySize, SM_TOTAL);

    const int total = E * NTAPS * 8 * 8 * 32;
    prep_weights_kernel<<<(total + 255) / 256, 256>>>(wgt);

    dim3 grid(HO / 2, E * Bn);  // (31, 128)
    conv_tf32_kernel<<<grid, 256, SM_TOTAL>>>(feat, bias, out);
}

// round 12
// speedup vs baseline: 1.6673x; 1.6673x over previous
#include <cuda_runtime.h>
#include <cuda_fp16.h>
#include <cstdint>
#include <cstddef>

// ---------------- problem constants ----------------
constexpr int E    = 4;
constexpr int Bn   = 32;
constexpr int CIN  = 64;
constexpr int H    = 64;
constexpr int W    = 64;
constexpr int COUT = 128;
constexpr int HO   = 62;
constexpr int WO   = 62;
constexpr int NTAPS = 9;

// ---------------- SMEM layout (byte offsets) ----------------
// G: transposed features [264 pos][64 ch] fp16, 128B rows, XOR-16B swizzle; hi+lo
constexpr int SM_GHI   = 0;          // 33792 B
constexpr int SM_GLO   = 33792;      // 33792 B
// Weight buffers (hi only, 144B row pitch): 18432 B each, double-buffered
constexpr int SM_W0    = 67584;
constexpr int SM_W1    = 86016;
// stage fp32 chunk (32 ch x 257 words = 32896 B) unions with W0+W1 (prologue only)
constexpr int SM_STAGE = 67584;
constexpr int SM_BIAS  = 104448;     // 512 B
constexpr int SM_TOTAL = 104960;     // x2 blocks = 209920 <= 228KB

constexpr int WBLK = 18432;          // bytes per (e,tap): hi only, 144B pitch

// ---------------- prepped weights (fp16 hi, 144B pitch) ----------------
__device__ __align__(16) unsigned char g_wprep[E * NTAPS * WBLK];

__global__ void prep_weights_kernel(const float* __restrict__ wgt) {
    int idx = blockIdx.x * blockDim.x + threadIdx.x;
    if (idx >= E * NTAPS * COUT * CIN) return;
    int i    = idx & 63;          // input channel (k index)
    int j    = (idx >> 6) & 127;  // cout (m index)
    int rest = idx >> 13;
    int tap  = rest % NTAPS;
    int e    = rest / NTAPS;

    float v = wgt[(((size_t)e * CIN + i) * COUT + j) * 9 + tap];
    size_t base = (size_t)(e * NTAPS + tap) * WBLK;
    *(__half*)(g_wprep + base + (size_t)j * 144 + i * 2) = __float2half(v);
}

// ---------------- PTX helpers (plain sm_80-class) ----------------
__device__ __forceinline__ uint32_t smem_u32(const void* p) {
    uint32_t a;
    asm("{ .reg .u64 t; cvta.to.shared.u64 t, %1; cvt.u32.u64 %0, t; }" : "=r"(a) : "l"(p));
    return a;
}
__device__ __forceinline__ void cpasync16(uint32_t dst, const void* src) {
    asm volatile("cp.async.cg.shared.global [%0], [%1], 16;" :: "r"(dst), "l"(src));
}
__device__ __forceinline__ void cpasync_commit() {
    asm volatile("cp.async.commit_group;" ::: "memory");
}
__device__ __forceinline__ void cpasync_wait0() {
    asm volatile("cp.async.wait_group 0;" ::: "memory");
}
__device__ __forceinline__ void cpasync_wait1() {
    asm volatile("cp.async.wait_group 1;" ::: "memory");
}
__device__ __forceinline__ void ldsm_x4(uint32_t& r0, uint32_t& r1, uint32_t& r2, uint32_t& r3,
                                        uint32_t addr) {
    asm volatile("ldmatrix.sync.aligned.m8n8.x4.shared.b16 {%0,%1,%2,%3}, [%4];"
                 : "=r"(r0), "=r"(r1), "=r"(r2), "=r"(r3) : "r"(addr));
}
__device__ __forceinline__ void mma16816(float* c, const uint32_t* a, uint32_t b0, uint32_t b1) {
    asm volatile(
        "mma.sync.aligned.m16n8k16.row.col.f32.f16.f16.f32 "
        "{%0,%1,%2,%3}, {%4,%5,%6,%7}, {%8,%9}, {%0,%1,%2,%3};"
        : "+f"(c[0]), "+f"(c[1]), "+f"(c[2]), "+f"(c[3])
        : "r"(a[0]), "r"(a[1]), "r"(a[2]), "r"(a[3]), "r"(b0), "r"(b1));
}

// ---------------- main kernel ----------------
// 256 threads (8 warps). jbase=(wid&1)*64 (couts), pbase=(wid>>1)*32 (pos).
// Per warp: 4 m16 x 4 n8 tiles; K=576 = 9 taps x 4 k16; 2 terms: wh*(fh + fl).
__global__ __launch_bounds__(256, 2)
void conv_hmma_kernel(const float* __restrict__ feat,
                      const float* __restrict__ bias,
                      float* __restrict__ out)
{
    extern __shared__ __align__(128) char smem[];
    const int tid  = threadIdx.x;
    const int wid  = tid >> 5;
    const int lane = tid & 31;
    const int eb   = blockIdx.y;
    const int e    = eb >> 5;
    const int y0   = blockIdx.x * 2;
    const uint32_t sb = smem_u32(smem);

    // --- 0) zero G pad rows (pos 256..263), load bias ---
    if (tid < 128) {
        ((uint2*)(smem + SM_GHI + 256 * 128))[tid] = make_uint2(0u, 0u);
        ((uint2*)(smem + SM_GLO + 256 * 128))[tid] = make_uint2(0u, 0u);
        ((float*)(smem + SM_BIAS))[tid] = bias[e * COUT + tid];
    }

    // --- 1) stage fp32 + build G (fp16 hi/lo, lo FTZ'd) in two 32-ch chunks ---
    const float* fb = feat + (size_t)eb * CIN * H * W + (size_t)y0 * W;
    float* sf = (float*)(smem + SM_STAGE);
#pragma unroll
    for (int q = 0; q < 2; q++) {
        __syncthreads();
#pragma unroll
        for (int c = 0; c < 32; c++) {
            int idx = c * 256 + tid;
            int i = idx >> 8, rx = idx & 255;
            sf[i * 257 + rx] = fb[(size_t)(q * 32 + i) * (H * W) + rx];
        }
        __syncthreads();
        const int ch    = q * 32 + lane;
        const int chnk  = (ch * 2) >> 4;
        const int cin16 = (ch * 2) & 15;
#pragma unroll
        for (int it = 0; it < 32; it++) {
            const int p = wid * 32 + it;
            float v = sf[lane * 257 + p];
            __half h = __float2half(v);
            float fl = v - __half2float(h);
            // flush below fp16 min-normal: keep every MMA operand normal-or-zero
            if (fabsf(fl) < 6.103515625e-5f) fl = 0.0f;
            uint32_t boff = (uint32_t)p * 128 + (uint32_t)((chnk ^ (p & 7)) << 4) + cin16;
            *(__half*)(smem + SM_GHI + boff) = h;
            *(__half*)(smem + SM_GLO + boff) = __float2half(fl);
        }
    }
    __syncthreads();   // stage dead: W0/W1 region free

    // --- 2) copy tap-0 weights into W0, prefetch tap-1 into W1 ---
    {
        const unsigned char* s0 = g_wprep + (size_t)(e * NTAPS) * WBLK;
#pragma unroll
        for (int c = 0; c < 5; c++) {
            int chunk = c * 256 + tid;
            if (chunk < 1152) cpasync16(sb + SM_W0 + chunk * 16, s0 + chunk * 16);
        }
        cpasync_commit();
        const unsigned char* s1 = s0 + WBLK;
#pragma unroll
        for (int c = 0; c < 5; c++) {
            int chunk = c * 256 + tid;
            if (chunk < 1152) cpasync16(sb + SM_W1 + chunk * 16, s1 + chunk * 16);
        }
        cpasync_commit();
    }

    // --- 3) main loop over 9 taps, double-buffered weights ---
    const int jbase = (wid & 1) * 64;
    const int pbase = (wid >> 1) * 32;
    const int tt = lane >> 3, r = lane & 7;
    const uint32_t aoff = (uint32_t)(((tt & 1) * 8 + r) * 144 + (tt >> 1) * 16);
    const int br  = (tt >> 1) * 8 + r;
    const int kcb = tt & 1;

    float acc[4][4][4];
#pragma unroll
    for (int a = 0; a < 4; a++)
#pragma unroll
        for (int b = 0; b < 4; b++)
#pragma unroll
            for (int c = 0; c < 4; c++) acc[a][b][c] = 0.0f;

    for (int t = 0; t < NTAPS; t++) {
        const uint32_t whi = sb + ((t & 1) ? SM_W1 : SM_W0);

        if (t == NTAPS - 1) cpasync_wait0(); else cpasync_wait1();
        __syncthreads();

        const int ky = t / 3, kx = t - ky * 3;
        const int pshift = pbase + ky * 64 + kx;

#pragma unroll
        for (int kq = 0; kq < 4; kq++) {
            const int k0 = kq * 16;
            uint32_t ah[4][4];
#pragma unroll
            for (int mt = 0; mt < 4; mt++) {
                uint32_t abase = (uint32_t)((jbase + mt * 16) * 144 + k0 * 2) + aoff;
                ldsm_x4(ah[mt][0], ah[mt][1], ah[mt][2], ah[mt][3], whi + abase);
            }
#pragma unroll
            for (int nt = 0; nt < 2; nt++) {
                const int P  = pshift + nt * 16 + br;
                const int kc = (k0 >> 3) + kcb;
                const uint32_t gb = (uint32_t)P * 128 + (uint32_t)((kc ^ (P & 7)) << 4);
                uint32_t bh[4], bl[4];
                ldsm_x4(bh[0], bh[1], bh[2], bh[3], sb + SM_GHI + gb);
                ldsm_x4(bl[0], bl[1], bl[2], bl[3], sb + SM_GLO + gb);
#pragma unroll
                for (int mt = 0; mt < 4; mt++) {
#pragma unroll
                    for (int sub = 0; sub < 2; sub++) {
                        float* c = acc[mt][nt * 2 + sub];
                        mma16816(c, ah[mt], bh[2 * sub], bh[2 * sub + 1]);
                        mma16816(c, ah[mt], bl[2 * sub], bl[2 * sub + 1]);
                    }
                }
            }
        }

        // prefetch tap t+2 into the buffer just consumed
        if (t + 2 <= NTAPS - 1) {
            __syncthreads();
            const unsigned char* src = g_wprep + (size_t)(e * NTAPS + t + 2) * WBLK;
#pragma unroll
            for (int c = 0; c < 5; c++) {
                int chunk = c * 256 + tid;
                if (chunk < 1152) cpasync16(whi + chunk * 16, src + chunk * 16);
            }
            cpasync_commit();
        }
    }

    // --- 4) epilogue: bias + float2 stores ---
    const float* sbias = (const float*)(smem + SM_BIAS);
#pragma unroll
    for (int mt = 0; mt < 4; mt++) {
        const int j0 = jbase + mt * 16 + (lane >> 2);
        const float b0 = sbias[j0];
        const float b1 = sbias[j0 + 8];
#pragma unroll
        for (int q = 0; q < 4; q++) {
            const int pos = pbase + q * 8 + 2 * (lane & 3);
            const int x = pos & 63;
            const int y = y0 + (pos >> 6);
            if (x < WO) {
                float2 v0 = make_float2(acc[mt][q][0] + b0, acc[mt][q][1] + b0);
                float2 v1 = make_float2(acc[mt][q][2] + b1, acc[mt][q][3] + b1);
                *(float2*)(out + (((size_t)eb * COUT + j0)     * HO + y) * WO + x) = v0;
                *(float2*)(out + (((size_t)eb * COUT + j0 + 8) * HO + y) * WO + x) = v1;
            }
        }
    }
}

// ---------------- launch ----------------
extern "C" void kernel_launch(void* const* d_in, const int* in_sizes, int n_in,
                              void* d_out, int out_size)
{
    const float* feat = (const float*)d_in[0];  // (E, B, C_in, H, W)
    const float* wgt  = (const float*)d_in[1];  // (E, C_in, C_out, 3, 3)
    const float* bias = (const float*)d_in[2];  // (E, C_out)
    float*       out  = (float*)d_out;          // (E, B, C_out, 62, 62)

    cudaFuncSetAttribute(conv_hmma_kernel,
                         cudaFuncAttributeMaxDynamicSharedMemorySize, SM_TOTAL);

    const int total = E * NTAPS * COUT * CIN;
    prep_weights_kernel<<<(total + 255) / 256, 256>>>(wgt);

    dim3 grid(HO / 2, E * Bn);  // (31, 128)
    conv_hmma_kernel<<<grid, 256, SM_TOTAL>>>(feat, bias, out);
}

// round 14
// speedup vs baseline: 2.6146x; 1.5682x over previous
#include <cuda_runtime.h>
#include <cuda_fp16.h>
#include <cstdint>
#include <cstddef>

// ---------------- problem constants ----------------
constexpr int E    = 4;
constexpr int Bn   = 32;
constexpr int CIN  = 64;
constexpr int H    = 64;
constexpr int W    = 64;
constexpr int COUT = 128;
constexpr int HO   = 62;
constexpr int WO   = 62;
constexpr int NTAPS = 9;

// ---------------- SMEM layout (byte offsets) ----------------
// G: transposed features [264 pos][64 ch] fp16, 128B rows, XOR-16B swizzle
constexpr int SM_GHI   = 0;          // 33792 B
// Weight buffers (fp16, 144B row pitch): 18432 B each, double-buffered
constexpr int SM_W0    = 33792;
constexpr int SM_W1    = 52224;
// stage fp32 chunk (32 ch x 257 words = 32896 B) unions with W0+W1 (prologue only)
constexpr int SM_STAGE = 33792;
constexpr int SM_BIAS  = 70656;      // 512 B
constexpr int SM_TOTAL = 71168;      // x2 blocks = 142336 <= 228KB

constexpr int WBLK = 18432;          // bytes per (e,tap), 144B pitch

// ---------------- prepped weights (fp16, 144B pitch) ----------------
__device__ __align__(16) unsigned char g_wprep[E * NTAPS * WBLK];

__global__ void prep_weights_kernel(const float* __restrict__ wgt) {
    int idx = blockIdx.x * blockDim.x + threadIdx.x;
    if (idx >= E * NTAPS * COUT * CIN) return;
    int i    = idx & 63;          // input channel (k index)
    int j    = (idx >> 6) & 127;  // cout (m index)
    int rest = idx >> 13;
    int tap  = rest % NTAPS;
    int e    = rest / NTAPS;

    float v = wgt[(((size_t)e * CIN + i) * COUT + j) * 9 + tap];
    size_t base = (size_t)(e * NTAPS + tap) * WBLK;
    *(__half*)(g_wprep + base + (size_t)j * 144 + i * 2) = __float2half(v);
}

// ---------------- PTX helpers (plain sm_80-class) ----------------
__device__ __forceinline__ uint32_t smem_u32(const void* p) {
    uint32_t a;
    asm("{ .reg .u64 t; cvta.to.shared.u64 t, %1; cvt.u32.u64 %0, t; }" : "=r"(a) : "l"(p));
    return a;
}
__device__ __forceinline__ void cpasync16(uint32_t dst, const void* src) {
    asm volatile("cp.async.cg.shared.global [%0], [%1], 16;" :: "r"(dst), "l"(src));
}
__device__ __forceinline__ void cpasync_commit() {
    asm volatile("cp.async.commit_group;" ::: "memory");
}
__device__ __forceinline__ void cpasync_wait0() {
    asm volatile("cp.async.wait_group 0;" ::: "memory");
}
__device__ __forceinline__ void cpasync_wait1() {
    asm volatile("cp.async.wait_group 1;" ::: "memory");
}
__device__ __forceinline__ void ldsm_x4(uint32_t& r0, uint32_t& r1, uint32_t& r2, uint32_t& r3,
                                        uint32_t addr) {
    asm volatile("ldmatrix.sync.aligned.m8n8.x4.shared.b16 {%0,%1,%2,%3}, [%4];"
                 : "=r"(r0), "=r"(r1), "=r"(r2), "=r"(r3) : "r"(addr));
}
__device__ __forceinline__ void mma16816(float* c, const uint32_t* a, uint32_t b0, uint32_t b1) {
    asm volatile(
        "mma.sync.aligned.m16n8k16.row.col.f32.f16.f16.f32 "
        "{%0,%1,%2,%3}, {%4,%5,%6,%7}, {%8,%9}, {%0,%1,%2,%3};"
        : "+f"(c[0]), "+f"(c[1]), "+f"(c[2]), "+f"(c[3])
        : "r"(a[0]), "r"(a[1]), "r"(a[2]), "r"(a[3]), "r"(b0), "r"(b1));
}

// ---------------- main kernel ----------------
// 256 threads (8 warps). jbase=(wid&1)*64 (couts), pbase=(wid>>1)*32 (pos).
// Per warp: 4 m16 x 4 n8 tiles; K=576 = 9 taps x 4 k16; single fp16 term.
__global__ __launch_bounds__(256, 2)
void conv_hmma_kernel(const float* __restrict__ feat,
                      const float* __restrict__ bias,
                      float* __restrict__ out)
{
    extern __shared__ __align__(128) char smem[];
    const int tid  = threadIdx.x;
    const int wid  = tid >> 5;
    const int lane = tid & 31;
    const int eb   = blockIdx.y;
    const int e    = eb >> 5;
    const int y0   = blockIdx.x * 2;
    const uint32_t sb = smem_u32(smem);

    // --- 0) zero G pad rows (pos 256..263), load bias ---
    if (tid < 128) {
        ((uint2*)(smem + SM_GHI + 256 * 128))[tid] = make_uint2(0u, 0u);
        ((float*)(smem + SM_BIAS))[tid] = bias[e * COUT + tid];
    }

    // --- 1) stage fp32 + build G (fp16) in two 32-channel chunks ---
    const float* fb = feat + (size_t)eb * CIN * H * W + (size_t)y0 * W;
    float* sf = (float*)(smem + SM_STAGE);
#pragma unroll
    for (int q = 0; q < 2; q++) {
        __syncthreads();
#pragma unroll
        for (int c = 0; c < 32; c++) {
            int idx = c * 256 + tid;
            int i = idx >> 8, rx = idx & 255;
            sf[i * 257 + rx] = fb[(size_t)(q * 32 + i) * (H * W) + rx];
        }
        __syncthreads();
        const int ch    = q * 32 + lane;
        const int chnk  = (ch * 2) >> 4;
        const int cin16 = (ch * 2) & 15;
#pragma unroll
        for (int it = 0; it < 32; it++) {
            const int p = wid * 32 + it;
            float v = sf[lane * 257 + p];
            uint32_t boff = (uint32_t)p * 128 + (uint32_t)((chnk ^ (p & 7)) << 4) + cin16;
            *(__half*)(smem + SM_GHI + boff) = __float2half(v);
        }
    }
    __syncthreads();   // stage dead: W0/W1 region free

    // --- 2) copy tap-0 weights into W0, prefetch tap-1 into W1 ---
    {
        const unsigned char* s0 = g_wprep + (size_t)(e * NTAPS) * WBLK;
#pragma unroll
        for (int c = 0; c < 5; c++) {
            int chunk = c * 256 + tid;
            if (chunk < 1152) cpasync16(sb + SM_W0 + chunk * 16, s0 + chunk * 16);
        }
        cpasync_commit();
        const unsigned char* s1 = s0 + WBLK;
#pragma unroll
        for (int c = 0; c < 5; c++) {
            int chunk = c * 256 + tid;
            if (chunk < 1152) cpasync16(sb + SM_W1 + chunk * 16, s1 + chunk * 16);
        }
        cpasync_commit();
    }

    // --- 3) main loop over 9 taps, double-buffered weights ---
    const int jbase = (wid & 1) * 64;
    const int pbase = (wid >> 1) * 32;
    const int tt = lane >> 3, r = lane & 7;
    const uint32_t aoff = (uint32_t)(((tt & 1) * 8 + r) * 144 + (tt >> 1) * 16);
    const int br  = (tt >> 1) * 8 + r;
    const int kcb = tt & 1;

    float acc[4][4][4];
#pragma unroll
    for (int a = 0; a < 4; a++)
#pragma unroll
        for (int b = 0; b < 4; b++)
#pragma unroll
            for (int c = 0; c < 4; c++) acc[a][b][c] = 0.0f;

    for (int t = 0; t < NTAPS; t++) {
        const uint32_t whi = sb + ((t & 1) ? SM_W1 : SM_W0);

        if (t == NTAPS - 1) cpasync_wait0(); else cpasync_wait1();
        __syncthreads();

        const int ky = t / 3, kx = t - ky * 3;
        const int pshift = pbase + ky * 64 + kx;

#pragma unroll
        for (int kq = 0; kq < 4; kq++) {
            const int k0 = kq * 16;
            uint32_t ah[4][4];
#pragma unroll
            for (int mt = 0; mt < 4; mt++) {
                uint32_t abase = (uint32_t)((jbase + mt * 16) * 144 + k0 * 2) + aoff;
                ldsm_x4(ah[mt][0], ah[mt][1], ah[mt][2], ah[mt][3], whi + abase);
            }
#pragma unroll
            for (int nt = 0; nt < 2; nt++) {
                const int P  = pshift + nt * 16 + br;
                const int kc = (k0 >> 3) + kcb;
                const uint32_t gb = (uint32_t)P * 128 + (uint32_t)((kc ^ (P & 7)) << 4);
                uint32_t bh[4];
                ldsm_x4(bh[0], bh[1], bh[2], bh[3], sb + SM_GHI + gb);
#pragma unroll
                for (int mt = 0; mt < 4; mt++) {
#pragma unroll
                    for (int sub = 0; sub < 2; sub++) {
                        mma16816(acc[mt][nt * 2 + sub], ah[mt],
                                 bh[2 * sub], bh[2 * sub + 1]);
                    }
                }
            }
        }

        // prefetch tap t+2 into the buffer just consumed
        if (t + 2 <= NTAPS - 1) {
            __syncthreads();
            const unsigned char* src = g_wprep + (size_t)(e * NTAPS + t + 2) * WBLK;
#pragma unroll
            for (int c = 0; c < 5; c++) {
                int chunk = c * 256 + tid;
                if (chunk < 1152) cpasync16(whi + chunk * 16, src + chunk * 16);
            }
            cpasync_commit();
        }
    }

    // --- 4) epilogue: bias + float2 stores ---
    const float* sbias = (const float*)(smem + SM_BIAS);
#pragma unroll
    for (int mt = 0; mt < 4; mt++) {
        const int j0 = jbase + mt * 16 + (lane >> 2);
        const float b0 = sbias[j0];
        const float b1 = sbias[j0 + 8];
#pragma unroll
        for (int q = 0; q < 4; q++) {
            const int pos = pbase + q * 8 + 2 * (lane & 3);
            const int x = pos & 63;
            const int y = y0 + (pos >> 6);
            if (x < WO) {
                float2 v0 = make_float2(acc[mt][q][0] + b0, acc[mt][q][1] + b0);
                float2 v1 = make_float2(acc[mt][q][2] + b1, acc[mt][q][3] + b1);
                *(float2*)(out + (((size_t)eb * COUT + j0)     * HO + y) * WO + x) = v0;
                *(float2*)(out + (((size_t)eb * COUT + j0 + 8) * HO + y) * WO + x) = v1;
            }
        }
    }
}

// ---------------- launch ----------------
extern "C" void kernel_launch(void* const* d_in, const int* in_sizes, int n_in,
                              void* d_out, int out_size)
{
    const float* feat = (const float*)d_in[0];  // (E, B, C_in, H, W)
    const float* wgt  = (const float*)d_in[1];  // (E, C_in, C_out, 3, 3)
    const float* bias = (const float*)d_in[2];  // (E, C_out)
    float*       out  = (float*)d_out;          // (E, B, C_out, 62, 62)

    cudaFuncSetAttribute(conv_hmma_kernel,
                         cudaFuncAttributeMaxDynamicSharedMemorySize, SM_TOTAL);

    const int total = E * NTAPS * COUT * CIN;
    prep_weights_kernel<<<(total + 255) / 256, 256>>>(wgt);

    dim3 grid(HO / 2, E * Bn);  // (31, 128)
    conv_hmma_kernel<<<grid, 256, SM_TOTAL>>>(feat, bias, out);
}